// round 7
// baseline (speedup 1.0000x reference)
#include <cuda_runtime.h>
#include <cuda_bf16.h>
#include <math.h>
#include <stdint.h>

#define Bz  32
#define Tz  512
#define INz 128
#define Hz  256
#define G3H 768
#define NHEADz 4
#define HDz 64
#define Cz 8

// ---------------- device scratch ----------------
__device__ float d_xp   [Bz*Tz*G3H];
__device__ float d_g0   [Bz*Tz*Hz];
__device__ float d_g1   [Bz*Tz*Hz];
__device__ float d_hh   [Bz*Tz*Hz];
__device__ float d_fs   [Bz*Tz*NHEADz];
__device__ float d_fd   [Bz*Tz*NHEADz];
__device__ float d_gato [Bz*Tz*Hz];
__device__ float d_y    [Bz*Tz*Hz];
__device__ float d_qkv  [Bz*Tz*G3H];
__device__ float d_scores[(long)Bz*NHEADz*Tz*Tz];
__device__ float d_ctx  [Bz*Tz*Hz];
__device__ float d_ao   [Bz*Tz*Hz];
__device__ float d_wcat [Hz*Hz];

// ---------------- tiled GEMM: 128x64 tile, 8x4 micro, double-buffered ----------------
// Requires M%128==0, N%64==0, K%16==0 (true for all call sites).
template<bool TRANSB>
__global__ void __launch_bounds__(256) gemm_tiled(
    const float* __restrict__ A, const float* __restrict__ Bm,
    const float* __restrict__ bias, float* __restrict__ C,
    int M, int N, int K, int lda, int ldb, int ldc, float alpha,
    long oAb, long oAh, long oBb, long oBh, long oCb, long oCh, int nH)
{
    int z = blockIdx.z;
    int zb = z / nH, zh = z - zb*nH;
    const float* Ab = A  + zb*oAb + zh*oAh;
    const float* Bb = Bm + zb*oBb + zh*oBh;
    float*       Cb = C  + zb*oCb + zh*oCh;

    __shared__ float As[2][16][132];
    __shared__ float Bs[2][16][68];

    int tid = threadIdx.x;
    int tx = tid & 15, ty = tid >> 4;
    int m0 = blockIdx.y * 128, n0 = blockIdx.x * 64;

    // loaders
    int ak  = (tid & 3) * 4;     // k offset (float4)
    int am  = tid >> 2;          // 0..63 (A row; +64 for second half)
    int bn  = tid >> 2;          // 0..63 (B row, TRANSB)
    int nk  = tid >> 4;          // 0..15 (B k row, non-TRANSB)
    int nn4 = (tid & 15) * 4;    // B n offset (non-TRANSB)

    const float* Aptr  = Ab + (long)(m0 + am) * lda + ak;
    const float* Aptr2 = Aptr + (long)64 * lda;
    const float* Bptr  = TRANSB ? (Bb + (long)(n0 + bn) * ldb + ak)
                                : (Bb + (long)nk * ldb + n0 + nn4);

    float4 a0 = *(const float4*)Aptr;
    float4 a1 = *(const float4*)Aptr2;
    float4 b0 = *(const float4*)Bptr;

    // stage 0
    As[0][ak+0][am] = a0.x; As[0][ak+1][am] = a0.y; As[0][ak+2][am] = a0.z; As[0][ak+3][am] = a0.w;
    As[0][ak+0][am+64] = a1.x; As[0][ak+1][am+64] = a1.y; As[0][ak+2][am+64] = a1.z; As[0][ak+3][am+64] = a1.w;
    if (TRANSB) {
        Bs[0][ak+0][bn] = b0.x; Bs[0][ak+1][bn] = b0.y; Bs[0][ak+2][bn] = b0.z; Bs[0][ak+3][bn] = b0.w;
    } else {
        *(float4*)&Bs[0][nk][nn4] = b0;
    }
    __syncthreads();

    int KB = K >> 4;
    float acc[8][4] = {};

    for (int kb = 0; kb < KB; kb++) {
        int cur = kb & 1;
        bool more = (kb + 1 < KB);
        if (more) {
            Aptr += 16; Aptr2 += 16;
            if (TRANSB) Bptr += 16; else Bptr += (long)16 * ldb;
            a0 = *(const float4*)Aptr;
            a1 = *(const float4*)Aptr2;
            b0 = *(const float4*)Bptr;
        }
        #pragma unroll
        for (int kk = 0; kk < 16; kk++) {
            float a[8], b[4];
            *(float4*)(a)     = *(const float4*)&As[cur][kk][ty*8];
            *(float4*)(a + 4) = *(const float4*)&As[cur][kk][ty*8 + 4];
            *(float4*)(b)     = *(const float4*)&Bs[cur][kk][tx*4];
            #pragma unroll
            for (int i = 0; i < 8; i++)
                #pragma unroll
                for (int j = 0; j < 4; j++)
                    acc[i][j] += a[i] * b[j];
        }
        if (more) {
            int nxt = cur ^ 1;
            As[nxt][ak+0][am] = a0.x; As[nxt][ak+1][am] = a0.y; As[nxt][ak+2][am] = a0.z; As[nxt][ak+3][am] = a0.w;
            As[nxt][ak+0][am+64] = a1.x; As[nxt][ak+1][am+64] = a1.y; As[nxt][ak+2][am+64] = a1.z; As[nxt][ak+3][am+64] = a1.w;
            if (TRANSB) {
                Bs[nxt][ak+0][bn] = b0.x; Bs[nxt][ak+1][bn] = b0.y; Bs[nxt][ak+2][bn] = b0.z; Bs[nxt][ak+3][bn] = b0.w;
            } else {
                *(float4*)&Bs[nxt][nk][nn4] = b0;
            }
        }
        __syncthreads();
    }

    float bb[4] = {0.f, 0.f, 0.f, 0.f};
    if (bias) {
        #pragma unroll
        for (int j = 0; j < 4; j++) bb[j] = bias[n0 + tx*4 + j];
    }
    #pragma unroll
    for (int i = 0; i < 8; i++) {
        int m = m0 + ty*8 + i;
        float4 v;
        v.x = alpha*acc[i][0] + bb[0];
        v.y = alpha*acc[i][1] + bb[1];
        v.z = alpha*acc[i][2] + bb[2];
        v.w = alpha*acc[i][3] + bb[3];
        *(float4*)&Cb[(long)m*ldc + n0 + tx*4] = v;
    }
}

// ---------------- GRU recurrence ----------------
__device__ __forceinline__ float sigm(float x) { return 1.f / (1.f + __expf(-x)); }

__device__ __forceinline__ unsigned long long fma2(unsigned long long a,
                                                   unsigned long long b,
                                                   unsigned long long c) {
    unsigned long long d;
    asm("fma.rn.f32x2 %0, %1, %2, %3;" : "=l"(d) : "l"(a), "l"(b), "l"(c));
    return d;
}
__device__ __forceinline__ unsigned long long add2(unsigned long long a,
                                                   unsigned long long b) {
    unsigned long long d;
    asm("add.rn.f32x2 %0, %1, %2;" : "=l"(d) : "l"(a), "l"(b));
    return d;
}
__device__ __forceinline__ unsigned int ld_acq_shared(uint32_t addr) {
    unsigned int v;
    asm volatile("ld.acquire.cluster.shared::cta.u32 %0, [%1];"
                 : "=r"(v) : "r"(addr) : "memory");
    return v;
}

// Thread map: khalf = wid&1 (warp-uniform -> broadcast LDS), r_local = (wid>>1)*32+lane.
// Sync: release/acquire sequence flags instead of barrier.cluster.
__global__ void __cluster_dims__(4,1,1) __launch_bounds__(384,1)
gru_layer_kernel(const float* __restrict__ xp, const float* __restrict__ W_hh,
                 const float* __restrict__ b_hh, float* __restrict__ gout)
{
    __shared__ __align__(16) float h_buf[2][256];
    __shared__ float gate_part[2][192];
    __shared__ unsigned int flags[4];   // flags[src] = steps completed by source CTA src

    int tid = threadIdx.x;
    unsigned c;
    asm("mov.u32 %0, %%cluster_ctarank;" : "=r"(c));
    int b = blockIdx.x >> 2;

    int wid  = tid >> 5, lane = tid & 31;
    int khalf   = wid & 1;
    int r_local = (wid >> 1) * 32 + lane;   // 0..191
    int gate    = r_local >> 6;             // 0=r 1=z 2=n
    int iloc    = r_local & 63;
    int row     = gate*256 + (int)c*64 + iloc;

    unsigned long long wreg2[64];
    {
        const unsigned long long* wp =
            (const unsigned long long*)(W_hh + (long)row*256 + khalf*128);
        #pragma unroll
        for (int kk = 0; kk < 64; kk++) wreg2[kk] = wp[kk];
    }
    float bh = (khalf == 0) ? b_hh[row] : 0.f;

    if (tid < 256) { h_buf[0][tid] = 0.f; h_buf[1][tid] = 0.f; }
    if (tid < 4) flags[tid] = 0u;
    uint32_t flags_base = (uint32_t)__cvta_generic_to_shared(&flags[0]);
    asm volatile("barrier.cluster.arrive.aligned;" ::: "memory");
    asm volatile("barrier.cluster.wait.aligned;"   ::: "memory");

    const float* xpb = xp   + (long)b*Tz*G3H;
    float*       gob = gout + (long)b*Tz*Hz;

    // x prefetch for t=0
    float xr = 0.f, xz = 0.f, xn = 0.f;
    if (tid < 64) {
        const float* xpt = xpb + (int)c*64 + tid;
        xr = xpt[0]; xz = xpt[256]; xn = xpt[512];
    }

    for (int t = 0; t < Tz; t++) {
        int cur = t & 1;
        if (t > 0) {
            // wait until all 4 source CTAs have published h(t)
            unsigned int tt = (unsigned int)t;
            for (;;) {
                unsigned int f0 = ld_acq_shared(flags_base);
                unsigned int f1 = ld_acq_shared(flags_base + 4);
                unsigned int f2 = ld_acq_shared(flags_base + 8);
                unsigned int f3 = ld_acq_shared(flags_base + 12);
                if (f0 >= tt && f1 >= tt && f2 >= tt && f3 >= tt) break;
            }
        }
        float hprev = 0.f;
        if (tid < 64) hprev = h_buf[cur][(int)c*64 + tid];

        // h @ W_hh^T : broadcast LDS + packed fma2, 4 accumulators
        unsigned long long acc2[4] = {0ull, 0ull, 0ull, 0ull};
        const ulonglong2* h2 = (const ulonglong2*)(&h_buf[cur][khalf*128]);
        #pragma unroll
        for (int q = 0; q < 32; q++) {
            ulonglong2 hv = h2[q];
            acc2[(2*q) & 3]   = fma2(wreg2[2*q],   hv.x, acc2[(2*q) & 3]);
            acc2[(2*q+1) & 3] = fma2(wreg2[2*q+1], hv.y, acc2[(2*q+1) & 3]);
        }
        unsigned long long s2 = add2(add2(acc2[0], acc2[1]), add2(acc2[2], acc2[3]));
        float2 sf = *(float2*)&s2;
        gate_part[khalf][r_local] = sf.x + sf.y + bh;
        __syncthreads();

        if (tid < 64) {
            float gr = gate_part[0][tid]       + gate_part[1][tid];
            float gz = gate_part[0][64 + tid]  + gate_part[1][64 + tid];
            float gn = gate_part[0][128 + tid] + gate_part[1][128 + tid];
            float r  = sigm(xr + gr);
            float zg = sigm(xz + gz);
            float n  = __tanhf(xn + r*gn);
            float hn = (1.f - zg)*n + zg*hprev;
            gob[(long)t*Hz + (int)c*64 + tid] = hn;
            if (t < Tz - 1) {
                int nxt = cur ^ 1;
                uint32_t laddr = (uint32_t)__cvta_generic_to_shared(&h_buf[nxt][(int)c*64 + tid]);
                #pragma unroll
                for (int p = 0; p < 4; p++) {
                    uint32_t ra;
                    asm volatile("mapa.shared::cluster.u32 %0, %1, %2;" : "=r"(ra) : "r"(laddr), "r"(p));
                    asm volatile("st.shared::cluster.f32 [%0], %1;" :: "r"(ra), "f"(hn) : "memory");
                }
                // prefetch x for t+1
                const float* xpt = xpb + (long)(t+1)*G3H + (int)c*64 + tid;
                xr = xpt[0]; xz = xpt[256]; xn = xpt[512];
                // all 64 h-stores done -> publish flag (release) to every CTA
                asm volatile("bar.sync 1, 64;" ::: "memory");
                if (tid == 0) {
                    unsigned int val = (unsigned int)(t + 1);
                    uint32_t lf = flags_base + (uint32_t)c * 4u;
                    #pragma unroll
                    for (int p = 0; p < 4; p++) {
                        uint32_t rf;
                        asm volatile("mapa.shared::cluster.u32 %0, %1, %2;" : "=r"(rf) : "r"(lf), "r"(p));
                        asm volatile("st.release.cluster.shared::cluster.u32 [%0], %1;"
                                     :: "r"(rf), "r"(val) : "memory");
                    }
                }
            }
        }
    }
    asm volatile("barrier.cluster.arrive.aligned;" ::: "memory");
    asm volatile("barrier.cluster.wait.aligned;"   ::: "memory");
}

// ---------------- GAT weight pack ----------------
__global__ void pack_gatw_kernel(const float* __restrict__ gw, float* __restrict__ wcat)
{
    int idx = blockIdx.x*256 + threadIdx.x;   // 65536
    int n = idx >> 8, k = idx & 255;
    int head = n >> 6, o = n & 63;
    wcat[idx] = gw[head*(256*64) + k*64 + o];
}

// ---------------- f_src / f_dst ----------------
__global__ void fsfd_kernel(const float* __restrict__ hh, const float* __restrict__ ga,
                            float* __restrict__ fs, float* __restrict__ fd)
{
    int idx = blockIdx.x*256 + threadIdx.x;   // B*T*4
    int bt = idx >> 2, head = idx & 3;
    const float* hp = hh + (long)bt*Hz + head*64;
    const float* ap = ga + head*128;
    float s = 0.f, dsum = 0.f;
    #pragma unroll 8
    for (int o = 0; o < 64; o++) { float v = hp[o]; s += v*ap[o]; dsum += v*ap[64+o]; }
    fs[idx] = s; fd[idx] = dsum;
}

// ---------------- fused GAT attention ----------------
#define GAT_SMEM_BYTES (512*64*4 + 8*512*4*4 + 512*4 + 512*4)
__global__ void __launch_bounds__(256,1) gat_attn_kernel(
    const float* __restrict__ hh, const float* __restrict__ fs,
    const float* __restrict__ fd, float* __restrict__ gato)
{
    extern __shared__ float sm[];
    float* hs    = sm;                  // 512*64
    float* wbuf  = sm + 512*64;         // 8 warps * 512 * 4
    float* fs_s  = wbuf + 8*512*4;      // 512
    float* fd_s  = fs_s + 512;          // 512
    __shared__ float redbuf[8];
    __shared__ float maxfd_s;

    int b = blockIdx.x >> 2, head = blockIdx.x & 3;
    int tid = threadIdx.x, lane = tid & 31, warp = tid >> 5;

    const float* hhb = hh + ((long)b*Tz)*Hz + head*64;
    for (int idx = tid; idx < 512*64; idx += 256) {
        int j = idx >> 6, d = idx & 63;
        hs[idx] = hhb[(long)j*Hz + d];
    }
    for (int j = tid; j < 512; j += 256) {
        fs_s[j] = fs[((long)b*Tz + j)*NHEADz + head];
        fd_s[j] = fd[((long)b*Tz + j)*NHEADz + head];
    }
    __syncthreads();

    float mloc = -INFINITY;
    for (int j = tid; j < 512; j += 256) mloc = fmaxf(mloc, fd_s[j]);
    #pragma unroll
    for (int o = 16; o; o >>= 1) mloc = fmaxf(mloc, __shfl_xor_sync(~0u, mloc, o));
    if (lane == 0) redbuf[warp] = mloc;
    __syncthreads();
    if (tid == 0) {
        float m = redbuf[0];
        #pragma unroll
        for (int i = 1; i < 8; i++) m = fmaxf(m, redbuf[i]);
        maxfd_s = m;
    }
    __syncthreads();
    float maxfd = maxfd_s;

    float* wb = wbuf + warp*512*4;
    const float2* hs2 = (const float2*)hs;

    for (int pass = 0; pass < 16; pass++) {
        int i0 = warp*64 + pass*4;
        float fsv[4], mi[4], ssum[4] = {0.f,0.f,0.f,0.f};
        #pragma unroll
        for (int ii = 0; ii < 4; ii++) {
            fsv[ii] = fs_s[i0 + ii];
            float mm = fsv[ii] + maxfd;
            mi[ii] = mm > 0.f ? mm : 0.2f*mm;
        }
        for (int j = lane; j < 512; j += 32) {
            float fdv = fd_s[j];
            float4 wv; float e;
            e = fsv[0] + fdv; e = e > 0.f ? e : 0.2f*e; wv.x = __expf(e - mi[0]); ssum[0] += wv.x;
            e = fsv[1] + fdv; e = e > 0.f ? e : 0.2f*e; wv.y = __expf(e - mi[1]); ssum[1] += wv.y;
            e = fsv[2] + fdv; e = e > 0.f ? e : 0.2f*e; wv.z = __expf(e - mi[2]); ssum[2] += wv.z;
            e = fsv[3] + fdv; e = e > 0.f ? e : 0.2f*e; wv.w = __expf(e - mi[3]); ssum[3] += wv.w;
            *(float4*)(wb + j*4) = wv;
        }
        #pragma unroll
        for (int ii = 0; ii < 4; ii++)
            #pragma unroll
            for (int o = 16; o; o >>= 1) ssum[ii] += __shfl_xor_sync(~0u, ssum[ii], o);
        float rinv[4];
        #pragma unroll
        for (int ii = 0; ii < 4; ii++) rinv[ii] = 1.f / ssum[ii];
        __syncwarp();

        float2 acc[4] = {{0.f,0.f},{0.f,0.f},{0.f,0.f},{0.f,0.f}};
        const float4* wb4 = (const float4*)wb;
        #pragma unroll 4
        for (int j = 0; j < 512; j++) {
            float4 wv = wb4[j];
            float2 hv = hs2[j*32 + lane];
            acc[0].x += wv.x*hv.x; acc[0].y += wv.x*hv.y;
            acc[1].x += wv.y*hv.x; acc[1].y += wv.y*hv.y;
            acc[2].x += wv.z*hv.x; acc[2].y += wv.z*hv.y;
            acc[3].x += wv.w*hv.x; acc[3].y += wv.w*hv.y;
        }
        #pragma unroll
        for (int ii = 0; ii < 4; ii++) {
            long o = ((long)b*Tz + i0 + ii)*Hz + head*64 + lane*2;
            float2 v; v.x = acc[ii].x*rinv[ii]; v.y = acc[ii].y*rinv[ii];
            *(float2*)(gato + o) = v;
        }
        __syncwarp();
    }
}

// ---------------- LayerNorm(g + gato) ----------------
__global__ void ln_kernel(const float* __restrict__ g, const float* __restrict__ go,
                          const float* __restrict__ gam, const float* __restrict__ bet,
                          float* __restrict__ y)
{
    int row = blockIdx.x*8 + (threadIdx.x >> 5);
    int lane = threadIdx.x & 31;
    const float* gp  = g  + (long)row*Hz + lane*8;
    const float* gop = go + (long)row*Hz + lane*8;
    float v[8]; float s = 0.f, ss = 0.f;
    #pragma unroll
    for (int k = 0; k < 8; k++) { v[k] = gp[k] + gop[k]; s += v[k]; ss += v[k]*v[k]; }
    #pragma unroll
    for (int o = 16; o; o >>= 1) {
        s  += __shfl_xor_sync(~0u, s,  o);
        ss += __shfl_xor_sync(~0u, ss, o);
    }
    float mu = s * (1.f/256.f);
    float var = ss * (1.f/256.f) - mu*mu;
    float rstd = rsqrtf(var + 1e-5f);
    float* yp = y + (long)row*Hz + lane*8;
    #pragma unroll
    for (int k = 0; k < 8; k++) {
        int col = lane*8 + k;
        yp[k] = (v[k] - mu) * rstd * gam[col] + bet[col];
    }
}

// ---------------- row softmax ----------------
__global__ void softmax_rows_kernel(float* __restrict__ s)
{
    long row = (long)blockIdx.x*8 + (threadIdx.x >> 5);
    int lane = threadIdx.x & 31;
    float4* p = (float4*)(s + row*512);
    float4 v[4];
    float m = -INFINITY;
    #pragma unroll
    for (int q = 0; q < 4; q++) {
        v[q] = p[lane + 32*q];
        m = fmaxf(m, fmaxf(fmaxf(v[q].x, v[q].y), fmaxf(v[q].z, v[q].w)));
    }
    #pragma unroll
    for (int o = 16; o; o >>= 1) m = fmaxf(m, __shfl_xor_sync(~0u, m, o));
    float sum = 0.f;
    #pragma unroll
    for (int q = 0; q < 4; q++) {
        v[q].x = __expf(v[q].x - m); v[q].y = __expf(v[q].y - m);
        v[q].z = __expf(v[q].z - m); v[q].w = __expf(v[q].w - m);
        sum += v[q].x + v[q].y + v[q].z + v[q].w;
    }
    #pragma unroll
    for (int o = 16; o; o >>= 1) sum += __shfl_xor_sync(~0u, sum, o);
    float r = 1.f / sum;
    #pragma unroll
    for (int q = 0; q < 4; q++) {
        v[q].x *= r; v[q].y *= r; v[q].z *= r; v[q].w *= r;
        p[lane + 32*q] = v[q];
    }
}

// ---------------- pooled head ----------------
__global__ void head_kernel(const float* __restrict__ ao,
                            const float* __restrict__ fc1w, const float* __restrict__ fc1b,
                            const float* __restrict__ fc2w, const float* __restrict__ fc2b,
                            float* __restrict__ out)
{
    __shared__ float pool[256];
    __shared__ float hid[128];
    int b = blockIdx.x, tid = threadIdx.x;
    float s = 0.f;
    const float* p = ao + (long)b*Tz*Hz + tid;
    for (int t = 0; t < Tz; t++) s += p[(long)t*Hz];
    pool[tid] = s * (1.f/512.f);
    __syncthreads();
    if (tid < 128) {
        float a = fc1b[tid];
        const float* w = fc1w + tid*256;
        #pragma unroll 8
        for (int k = 0; k < 256; k++) a += w[k]*pool[k];
        hid[tid] = fmaxf(a, 0.f);
    }
    __syncthreads();
    if (tid < 8) {
        float a = fc2b[tid];
        const float* w = fc2w + tid*128;
        #pragma unroll 8
        for (int k = 0; k < 128; k++) a += w[k]*hid[k];
        out[b*8 + tid] = a;
    }
}

// ---------------- launch ----------------
extern "C" void kernel_launch(void* const* d_in, const int* in_sizes, int n_in,
                              void* d_out, int out_size)
{
    const float* x         = (const float*)d_in[0];
    const float* W_ih0     = (const float*)d_in[1];
    const float* W_hh0     = (const float*)d_in[2];
    const float* b_ih0     = (const float*)d_in[3];
    const float* b_hh0     = (const float*)d_in[4];
    const float* W_ih1     = (const float*)d_in[5];
    const float* W_hh1     = (const float*)d_in[6];
    const float* b_ih1     = (const float*)d_in[7];
    const float* b_hh1     = (const float*)d_in[8];
    const float* gat_W     = (const float*)d_in[9];
    const float* gat_a     = (const float*)d_in[10];
    const float* ln_g      = (const float*)d_in[11];
    const float* ln_b      = (const float*)d_in[12];
    const float* mha_in_w  = (const float*)d_in[13];
    const float* mha_in_b  = (const float*)d_in[14];
    const float* mha_out_w = (const float*)d_in[15];
    const float* mha_out_b = (const float*)d_in[16];
    const float* fc1_w     = (const float*)d_in[17];
    const float* fc1_b     = (const float*)d_in[18];
    const float* fc2_w     = (const float*)d_in[19];
    const float* fc2_b     = (const float*)d_in[20];
    float* out = (float*)d_out;

    float *xp, *g0, *g1, *hh, *fs, *fd, *gato, *y, *qkv, *scores, *ctx, *ao, *wcat;
    cudaGetSymbolAddress((void**)&xp,     d_xp);
    cudaGetSymbolAddress((void**)&g0,     d_g0);
    cudaGetSymbolAddress((void**)&g1,     d_g1);
    cudaGetSymbolAddress((void**)&hh,     d_hh);
    cudaGetSymbolAddress((void**)&fs,     d_fs);
    cudaGetSymbolAddress((void**)&fd,     d_fd);
    cudaGetSymbolAddress((void**)&gato,   d_gato);
    cudaGetSymbolAddress((void**)&y,      d_y);
    cudaGetSymbolAddress((void**)&qkv,    d_qkv);
    cudaGetSymbolAddress((void**)&scores, d_scores);
    cudaGetSymbolAddress((void**)&ctx,    d_ctx);
    cudaGetSymbolAddress((void**)&ao,     d_ao);
    cudaGetSymbolAddress((void**)&wcat,   d_wcat);

    cudaFuncSetAttribute(gat_attn_kernel, cudaFuncAttributeMaxDynamicSharedMemorySize,
                         GAT_SMEM_BYTES);

    // xp0 = x @ W_ih0^T + b_ih0   (M=16384, N=768, K=128)
    gemm_tiled<true><<<dim3(12,128,1),256>>>(x, W_ih0, b_ih0, xp,
        Bz*Tz, G3H, INz, INz, INz, G3H, 1.f, 0,0,0,0,0,0, 1);
    // GRU layer 0
    gru_layer_kernel<<<128,384>>>(xp, W_hh0, b_hh0, g0);
    // xp1 = g0 @ W_ih1^T + b_ih1  (K=256)
    gemm_tiled<true><<<dim3(12,128,1),256>>>(g0, W_ih1, b_ih1, xp,
        Bz*Tz, G3H, Hz, Hz, Hz, G3H, 1.f, 0,0,0,0,0,0, 1);
    // GRU layer 1
    gru_layer_kernel<<<128,384>>>(xp, W_hh1, b_hh1, g1);

    // GAT projections
    pack_gatw_kernel<<<256,256>>>(gat_W, wcat);
    gemm_tiled<true><<<dim3(4,128,1),256>>>(g1, wcat, (const float*)0, hh,
        Bz*Tz, Hz, Hz, Hz, Hz, Hz, 1.f, 0,0,0,0,0,0, 1);
    fsfd_kernel<<<256,256>>>(hh, gat_a, fs, fd);
    gat_attn_kernel<<<128,256,GAT_SMEM_BYTES>>>(hh, fs, fd, gato);

    // y = LN(g1 + gat_out)
    ln_kernel<<<2048,256>>>(g1, gato, ln_g, ln_b, y);

    // qkv = y @ mha_in_w^T + b
    gemm_tiled<true><<<dim3(12,128,1),256>>>(y, mha_in_w, mha_in_b, qkv,
        Bz*Tz, G3H, Hz, Hz, Hz, G3H, 1.f, 0,0,0,0,0,0, 1);

    // scores = q @ k^T / 8   (batched over b,h; M=512,N=512,K=64)
    gemm_tiled<true><<<dim3(8,4,128),256>>>(qkv, qkv + 256, (const float*)0, scores,
        Tz, Tz, HDz, G3H, G3H, Tz, 0.125f,
        (long)Tz*G3H, 64L, (long)Tz*G3H, 64L,
        (long)NHEADz*Tz*Tz, (long)Tz*Tz, NHEADz);
    softmax_rows_kernel<<<8192,256>>>(scores);
    // ctx = attn @ v  (M=512,N=64,K=512)
    gemm_tiled<false><<<dim3(1,4,128),256>>>(scores, qkv + 512, (const float*)0, ctx,
        Tz, HDz, Tz, Tz, G3H, Hz, 1.f,
        (long)NHEADz*Tz*Tz, (long)Tz*Tz, (long)Tz*G3H, 64L,
        (long)Tz*Hz, 64L, NHEADz);
    // out-proj
    gemm_tiled<true><<<dim3(4,128,1),256>>>(ctx, mha_out_w, mha_out_b, ao,
        Bz*Tz, Hz, Hz, Hz, Hz, Hz, 1.f, 0,0,0,0,0,0, 1);

    // pooled -> fc1 -> fc2
    head_kernel<<<32,256>>>(ao, fc1_w, fc1_b, fc2_w, fc2_b, out);
}

// round 8
// speedup vs baseline: 1.0044x; 1.0044x over previous
#include <cuda_runtime.h>
#include <cuda_bf16.h>
#include <math.h>
#include <stdint.h>

#define Bz  32
#define Tz  512
#define INz 128
#define Hz  256
#define G3H 768
#define NHEADz 4
#define HDz 64
#define Cz 8

// ---------------- device scratch ----------------
__device__ float d_xp   [Bz*Tz*G3H];
__device__ float d_g0   [Bz*Tz*Hz];
__device__ float d_g1   [Bz*Tz*Hz];
__device__ float d_hh   [Bz*Tz*Hz];
__device__ float d_fs   [Bz*Tz*NHEADz];
__device__ float d_fd   [Bz*Tz*NHEADz];
__device__ float d_gato [Bz*Tz*Hz];
__device__ float d_y    [Bz*Tz*Hz];
__device__ float d_qkv  [Bz*Tz*G3H];
__device__ float d_scores[(long)Bz*NHEADz*Tz*Tz];
__device__ float d_ctx  [Bz*Tz*Hz];
__device__ float d_ao   [Bz*Tz*Hz];
__device__ float d_wcat [Hz*Hz];

// ---------------- tiled GEMM: 128x64 tile, 8x4 micro, double-buffered ----------------
// Requires M%128==0, N%64==0, K%16==0 (true for all call sites).
template<bool TRANSB>
__global__ void __launch_bounds__(256) gemm_tiled(
    const float* __restrict__ A, const float* __restrict__ Bm,
    const float* __restrict__ bias, float* __restrict__ C,
    int M, int N, int K, int lda, int ldb, int ldc, float alpha,
    long oAb, long oAh, long oBb, long oBh, long oCb, long oCh, int nH)
{
    int z = blockIdx.z;
    int zb = z / nH, zh = z - zb*nH;
    const float* Ab = A  + zb*oAb + zh*oAh;
    const float* Bb = Bm + zb*oBb + zh*oBh;
    float*       Cb = C  + zb*oCb + zh*oCh;

    __shared__ float As[2][16][132];
    __shared__ float Bs[2][16][68];

    int tid = threadIdx.x;
    int tx = tid & 15, ty = tid >> 4;
    int m0 = blockIdx.y * 128, n0 = blockIdx.x * 64;

    // loaders
    int ak  = (tid & 3) * 4;     // k offset (float4)
    int am  = tid >> 2;          // 0..63 (A row; +64 for second half)
    int bn  = tid >> 2;          // 0..63 (B row, TRANSB)
    int nk  = tid >> 4;          // 0..15 (B k row, non-TRANSB)
    int nn4 = (tid & 15) * 4;    // B n offset (non-TRANSB)

    const float* Aptr  = Ab + (long)(m0 + am) * lda + ak;
    const float* Aptr2 = Aptr + (long)64 * lda;
    const float* Bptr  = TRANSB ? (Bb + (long)(n0 + bn) * ldb + ak)
                                : (Bb + (long)nk * ldb + n0 + nn4);

    float4 a0 = *(const float4*)Aptr;
    float4 a1 = *(const float4*)Aptr2;
    float4 b0 = *(const float4*)Bptr;

    // stage 0
    As[0][ak+0][am] = a0.x; As[0][ak+1][am] = a0.y; As[0][ak+2][am] = a0.z; As[0][ak+3][am] = a0.w;
    As[0][ak+0][am+64] = a1.x; As[0][ak+1][am+64] = a1.y; As[0][ak+2][am+64] = a1.z; As[0][ak+3][am+64] = a1.w;
    if (TRANSB) {
        Bs[0][ak+0][bn] = b0.x; Bs[0][ak+1][bn] = b0.y; Bs[0][ak+2][bn] = b0.z; Bs[0][ak+3][bn] = b0.w;
    } else {
        *(float4*)&Bs[0][nk][nn4] = b0;
    }
    __syncthreads();

    int KB = K >> 4;
    float acc[8][4] = {};

    for (int kb = 0; kb < KB; kb++) {
        int cur = kb & 1;
        bool more = (kb + 1 < KB);
        if (more) {
            Aptr += 16; Aptr2 += 16;
            if (TRANSB) Bptr += 16; else Bptr += (long)16 * ldb;
            a0 = *(const float4*)Aptr;
            a1 = *(const float4*)Aptr2;
            b0 = *(const float4*)Bptr;
        }
        #pragma unroll
        for (int kk = 0; kk < 16; kk++) {
            float a[8], b[4];
            *(float4*)(a)     = *(const float4*)&As[cur][kk][ty*8];
            *(float4*)(a + 4) = *(const float4*)&As[cur][kk][ty*8 + 4];
            *(float4*)(b)     = *(const float4*)&Bs[cur][kk][tx*4];
            #pragma unroll
            for (int i = 0; i < 8; i++)
                #pragma unroll
                for (int j = 0; j < 4; j++)
                    acc[i][j] += a[i] * b[j];
        }
        if (more) {
            int nxt = cur ^ 1;
            As[nxt][ak+0][am] = a0.x; As[nxt][ak+1][am] = a0.y; As[nxt][ak+2][am] = a0.z; As[nxt][ak+3][am] = a0.w;
            As[nxt][ak+0][am+64] = a1.x; As[nxt][ak+1][am+64] = a1.y; As[nxt][ak+2][am+64] = a1.z; As[nxt][ak+3][am+64] = a1.w;
            if (TRANSB) {
                Bs[nxt][ak+0][bn] = b0.x; Bs[nxt][ak+1][bn] = b0.y; Bs[nxt][ak+2][bn] = b0.z; Bs[nxt][ak+3][bn] = b0.w;
            } else {
                *(float4*)&Bs[nxt][nk][nn4] = b0;
            }
        }
        __syncthreads();
    }

    float bb[4] = {0.f, 0.f, 0.f, 0.f};
    if (bias) {
        #pragma unroll
        for (int j = 0; j < 4; j++) bb[j] = bias[n0 + tx*4 + j];
    }
    #pragma unroll
    for (int i = 0; i < 8; i++) {
        int m = m0 + ty*8 + i;
        float4 v;
        v.x = alpha*acc[i][0] + bb[0];
        v.y = alpha*acc[i][1] + bb[1];
        v.z = alpha*acc[i][2] + bb[2];
        v.w = alpha*acc[i][3] + bb[3];
        *(float4*)&Cb[(long)m*ldc + n0 + tx*4] = v;
    }
}

// ---------------- GRU recurrence ----------------
__device__ __forceinline__ float sigm(float x) { return 1.f / (1.f + __expf(-x)); }

__device__ __forceinline__ unsigned long long fma2(unsigned long long a,
                                                   unsigned long long b,
                                                   unsigned long long c) {
    unsigned long long d;
    asm("fma.rn.f32x2 %0, %1, %2, %3;" : "=l"(d) : "l"(a), "l"(b), "l"(c));
    return d;
}
__device__ __forceinline__ unsigned long long add2(unsigned long long a,
                                                   unsigned long long b) {
    unsigned long long d;
    asm("add.rn.f32x2 %0, %1, %2;" : "=l"(d) : "l"(a), "l"(b));
    return d;
}
__device__ __forceinline__ unsigned int ld_acq_shared(uint32_t addr) {
    unsigned int v;
    asm volatile("ld.acquire.cluster.shared::cta.u32 %0, [%1];"
                 : "=r"(v) : "r"(addr) : "memory");
    return v;
}

// Thread map: khalf = wid&1 (warp-uniform -> broadcast LDS), r_local = (wid>>1)*32+lane.
// Sync: release/acquire sequence flags instead of barrier.cluster.
__global__ void __cluster_dims__(4,1,1) __launch_bounds__(384,1)
gru_layer_kernel(const float* __restrict__ xp, const float* __restrict__ W_hh,
                 const float* __restrict__ b_hh, float* __restrict__ gout)
{
    __shared__ __align__(16) float h_buf[2][256];
    __shared__ float gate_part[2][192];
    __shared__ unsigned int flags[4];   // flags[src] = steps completed by source CTA src

    int tid = threadIdx.x;
    unsigned c;
    asm("mov.u32 %0, %%cluster_ctarank;" : "=r"(c));
    int b = blockIdx.x >> 2;

    int wid  = tid >> 5, lane = tid & 31;
    int khalf   = wid & 1;
    int r_local = (wid >> 1) * 32 + lane;   // 0..191
    int gate    = r_local >> 6;             // 0=r 1=z 2=n
    int iloc    = r_local & 63;
    int row     = gate*256 + (int)c*64 + iloc;

    unsigned long long wreg2[64];
    {
        const unsigned long long* wp =
            (const unsigned long long*)(W_hh + (long)row*256 + khalf*128);
        #pragma unroll
        for (int kk = 0; kk < 64; kk++) wreg2[kk] = wp[kk];
    }
    float bh = (khalf == 0) ? b_hh[row] : 0.f;

    if (tid < 256) { h_buf[0][tid] = 0.f; h_buf[1][tid] = 0.f; }
    if (tid < 4) flags[tid] = 0u;
    uint32_t flags_base = (uint32_t)__cvta_generic_to_shared(&flags[0]);
    asm volatile("barrier.cluster.arrive.aligned;" ::: "memory");
    asm volatile("barrier.cluster.wait.aligned;"   ::: "memory");

    const float* xpb = xp   + (long)b*Tz*G3H;
    float*       gob = gout + (long)b*Tz*Hz;

    // x prefetch for t=0
    float xr = 0.f, xz = 0.f, xn = 0.f;
    if (tid < 64) {
        const float* xpt = xpb + (int)c*64 + tid;
        xr = xpt[0]; xz = xpt[256]; xn = xpt[512];
    }

    for (int t = 0; t < Tz; t++) {
        int cur = t & 1;
        if (t > 0) {
            // wait until all 4 source CTAs have published h(t)
            unsigned int tt = (unsigned int)t;
            for (;;) {
                unsigned int f0 = ld_acq_shared(flags_base);
                unsigned int f1 = ld_acq_shared(flags_base + 4);
                unsigned int f2 = ld_acq_shared(flags_base + 8);
                unsigned int f3 = ld_acq_shared(flags_base + 12);
                if (f0 >= tt && f1 >= tt && f2 >= tt && f3 >= tt) break;
            }
        }
        float hprev = 0.f;
        if (tid < 64) hprev = h_buf[cur][(int)c*64 + tid];

        // h @ W_hh^T : broadcast LDS + packed fma2, 4 accumulators
        unsigned long long acc2[4] = {0ull, 0ull, 0ull, 0ull};
        const ulonglong2* h2 = (const ulonglong2*)(&h_buf[cur][khalf*128]);
        #pragma unroll
        for (int q = 0; q < 32; q++) {
            ulonglong2 hv = h2[q];
            acc2[(2*q) & 3]   = fma2(wreg2[2*q],   hv.x, acc2[(2*q) & 3]);
            acc2[(2*q+1) & 3] = fma2(wreg2[2*q+1], hv.y, acc2[(2*q+1) & 3]);
        }
        unsigned long long s2 = add2(add2(acc2[0], acc2[1]), add2(acc2[2], acc2[3]));
        float2 sf = *(float2*)&s2;
        gate_part[khalf][r_local] = sf.x + sf.y + bh;
        __syncthreads();

        if (tid < 64) {
            float gr = gate_part[0][tid]       + gate_part[1][tid];
            float gz = gate_part[0][64 + tid]  + gate_part[1][64 + tid];
            float gn = gate_part[0][128 + tid] + gate_part[1][128 + tid];
            float r  = sigm(xr + gr);
            float zg = sigm(xz + gz);
            float n  = __tanhf(xn + r*gn);
            float hn = (1.f - zg)*n + zg*hprev;
            gob[(long)t*Hz + (int)c*64 + tid] = hn;
            if (t < Tz - 1) {
                int nxt = cur ^ 1;
                uint32_t laddr = (uint32_t)__cvta_generic_to_shared(&h_buf[nxt][(int)c*64 + tid]);
                #pragma unroll
                for (int p = 0; p < 4; p++) {
                    uint32_t ra;
                    asm volatile("mapa.shared::cluster.u32 %0, %1, %2;" : "=r"(ra) : "r"(laddr), "r"(p));
                    asm volatile("st.shared::cluster.f32 [%0], %1;" :: "r"(ra), "f"(hn) : "memory");
                }
                // prefetch x for t+1
                const float* xpt = xpb + (long)(t+1)*G3H + (int)c*64 + tid;
                xr = xpt[0]; xz = xpt[256]; xn = xpt[512];
                // all 64 h-stores done -> publish flag (release) to every CTA
                asm volatile("bar.sync 1, 64;" ::: "memory");
                if (tid == 0) {
                    unsigned int val = (unsigned int)(t + 1);
                    uint32_t lf = flags_base + (uint32_t)c * 4u;
                    #pragma unroll
                    for (int p = 0; p < 4; p++) {
                        uint32_t rf;
                        asm volatile("mapa.shared::cluster.u32 %0, %1, %2;" : "=r"(rf) : "r"(lf), "r"(p));
                        asm volatile("st.release.cluster.shared::cluster.u32 [%0], %1;"
                                     :: "r"(rf), "r"(val) : "memory");
                    }
                }
            }
        }
    }
    asm volatile("barrier.cluster.arrive.aligned;" ::: "memory");
    asm volatile("barrier.cluster.wait.aligned;"   ::: "memory");
}

// ---------------- GAT weight pack ----------------
__global__ void pack_gatw_kernel(const float* __restrict__ gw, float* __restrict__ wcat)
{
    int idx = blockIdx.x*256 + threadIdx.x;   // 65536
    int n = idx >> 8, k = idx & 255;
    int head = n >> 6, o = n & 63;
    wcat[idx] = gw[head*(256*64) + k*64 + o];
}

// ---------------- f_src / f_dst ----------------
__global__ void fsfd_kernel(const float* __restrict__ hh, const float* __restrict__ ga,
                            float* __restrict__ fs, float* __restrict__ fd)
{
    int idx = blockIdx.x*256 + threadIdx.x;   // B*T*4
    int bt = idx >> 2, head = idx & 3;
    const float* hp = hh + (long)bt*Hz + head*64;
    const float* ap = ga + head*128;
    float s = 0.f, dsum = 0.f;
    #pragma unroll 8
    for (int o = 0; o < 64; o++) { float v = hp[o]; s += v*ap[o]; dsum += v*ap[64+o]; }
    fs[idx] = s; fd[idx] = dsum;
}

// ---------------- fused GAT attention ----------------
#define GAT_SMEM_BYTES (512*64*4 + 8*512*4*4 + 512*4 + 512*4)
__global__ void __launch_bounds__(256,1) gat_attn_kernel(
    const float* __restrict__ hh, const float* __restrict__ fs,
    const float* __restrict__ fd, float* __restrict__ gato)
{
    extern __shared__ float sm[];
    float* hs    = sm;                  // 512*64
    float* wbuf  = sm + 512*64;         // 8 warps * 512 * 4
    float* fs_s  = wbuf + 8*512*4;      // 512
    float* fd_s  = fs_s + 512;          // 512
    __shared__ float redbuf[8];
    __shared__ float maxfd_s;

    int b = blockIdx.x >> 2, head = blockIdx.x & 3;
    int tid = threadIdx.x, lane = tid & 31, warp = tid >> 5;

    const float* hhb = hh + ((long)b*Tz)*Hz + head*64;
    for (int idx = tid; idx < 512*64; idx += 256) {
        int j = idx >> 6, d = idx & 63;
        hs[idx] = hhb[(long)j*Hz + d];
    }
    for (int j = tid; j < 512; j += 256) {
        fs_s[j] = fs[((long)b*Tz + j)*NHEADz + head];
        fd_s[j] = fd[((long)b*Tz + j)*NHEADz + head];
    }
    __syncthreads();

    float mloc = -INFINITY;
    for (int j = tid; j < 512; j += 256) mloc = fmaxf(mloc, fd_s[j]);
    #pragma unroll
    for (int o = 16; o; o >>= 1) mloc = fmaxf(mloc, __shfl_xor_sync(~0u, mloc, o));
    if (lane == 0) redbuf[warp] = mloc;
    __syncthreads();
    if (tid == 0) {
        float m = redbuf[0];
        #pragma unroll
        for (int i = 1; i < 8; i++) m = fmaxf(m, redbuf[i]);
        maxfd_s = m;
    }
    __syncthreads();
    float maxfd = maxfd_s;

    float* wb = wbuf + warp*512*4;
    const float2* hs2 = (const float2*)hs;

    for (int pass = 0; pass < 16; pass++) {
        int i0 = warp*64 + pass*4;
        float fsv[4], mi[4], ssum[4] = {0.f,0.f,0.f,0.f};
        #pragma unroll
        for (int ii = 0; ii < 4; ii++) {
            fsv[ii] = fs_s[i0 + ii];
            float mm = fsv[ii] + maxfd;
            mi[ii] = mm > 0.f ? mm : 0.2f*mm;
        }
        for (int j = lane; j < 512; j += 32) {
            float fdv = fd_s[j];
            float4 wv; float e;
            e = fsv[0] + fdv; e = e > 0.f ? e : 0.2f*e; wv.x = __expf(e - mi[0]); ssum[0] += wv.x;
            e = fsv[1] + fdv; e = e > 0.f ? e : 0.2f*e; wv.y = __expf(e - mi[1]); ssum[1] += wv.y;
            e = fsv[2] + fdv; e = e > 0.f ? e : 0.2f*e; wv.z = __expf(e - mi[2]); ssum[2] += wv.z;
            e = fsv[3] + fdv; e = e > 0.f ? e : 0.2f*e; wv.w = __expf(e - mi[3]); ssum[3] += wv.w;
            *(float4*)(wb + j*4) = wv;
        }
        #pragma unroll
        for (int ii = 0; ii < 4; ii++)
            #pragma unroll
            for (int o = 16; o; o >>= 1) ssum[ii] += __shfl_xor_sync(~0u, ssum[ii], o);
        float rinv[4];
        #pragma unroll
        for (int ii = 0; ii < 4; ii++) rinv[ii] = 1.f / ssum[ii];
        __syncwarp();

        float2 acc[4] = {{0.f,0.f},{0.f,0.f},{0.f,0.f},{0.f,0.f}};
        const float4* wb4 = (const float4*)wb;
        #pragma unroll 4
        for (int j = 0; j < 512; j++) {
            float4 wv = wb4[j];
            float2 hv = hs2[j*32 + lane];
            acc[0].x += wv.x*hv.x; acc[0].y += wv.x*hv.y;
            acc[1].x += wv.y*hv.x; acc[1].y += wv.y*hv.y;
            acc[2].x += wv.z*hv.x; acc[2].y += wv.z*hv.y;
            acc[3].x += wv.w*hv.x; acc[3].y += wv.w*hv.y;
        }
        #pragma unroll
        for (int ii = 0; ii < 4; ii++) {
            long o = ((long)b*Tz + i0 + ii)*Hz + head*64 + lane*2;
            float2 v; v.x = acc[ii].x*rinv[ii]; v.y = acc[ii].y*rinv[ii];
            *(float2*)(gato + o) = v;
        }
        __syncwarp();
    }
}

// ---------------- LayerNorm(g + gato) ----------------
__global__ void ln_kernel(const float* __restrict__ g, const float* __restrict__ go,
                          const float* __restrict__ gam, const float* __restrict__ bet,
                          float* __restrict__ y)
{
    int row = blockIdx.x*8 + (threadIdx.x >> 5);
    int lane = threadIdx.x & 31;
    const float* gp  = g  + (long)row*Hz + lane*8;
    const float* gop = go + (long)row*Hz + lane*8;
    float v[8]; float s = 0.f, ss = 0.f;
    #pragma unroll
    for (int k = 0; k < 8; k++) { v[k] = gp[k] + gop[k]; s += v[k]; ss += v[k]*v[k]; }
    #pragma unroll
    for (int o = 16; o; o >>= 1) {
        s  += __shfl_xor_sync(~0u, s,  o);
        ss += __shfl_xor_sync(~0u, ss, o);
    }
    float mu = s * (1.f/256.f);
    float var = ss * (1.f/256.f) - mu*mu;
    float rstd = rsqrtf(var + 1e-5f);
    float* yp = y + (long)row*Hz + lane*8;
    #pragma unroll
    for (int k = 0; k < 8; k++) {
        int col = lane*8 + k;
        yp[k] = (v[k] - mu) * rstd * gam[col] + bet[col];
    }
}

// ---------------- row softmax ----------------
__global__ void softmax_rows_kernel(float* __restrict__ s)
{
    long row = (long)blockIdx.x*8 + (threadIdx.x >> 5);
    int lane = threadIdx.x & 31;
    float4* p = (float4*)(s + row*512);
    float4 v[4];
    float m = -INFINITY;
    #pragma unroll
    for (int q = 0; q < 4; q++) {
        v[q] = p[lane + 32*q];
        m = fmaxf(m, fmaxf(fmaxf(v[q].x, v[q].y), fmaxf(v[q].z, v[q].w)));
    }
    #pragma unroll
    for (int o = 16; o; o >>= 1) m = fmaxf(m, __shfl_xor_sync(~0u, m, o));
    float sum = 0.f;
    #pragma unroll
    for (int q = 0; q < 4; q++) {
        v[q].x = __expf(v[q].x - m); v[q].y = __expf(v[q].y - m);
        v[q].z = __expf(v[q].z - m); v[q].w = __expf(v[q].w - m);
        sum += v[q].x + v[q].y + v[q].z + v[q].w;
    }
    #pragma unroll
    for (int o = 16; o; o >>= 1) sum += __shfl_xor_sync(~0u, sum, o);
    float r = 1.f / sum;
    #pragma unroll
    for (int q = 0; q < 4; q++) {
        v[q].x *= r; v[q].y *= r; v[q].z *= r; v[q].w *= r;
        p[lane + 32*q] = v[q];
    }
}

// ---------------- pooled head ----------------
__global__ void head_kernel(const float* __restrict__ ao,
                            const float* __restrict__ fc1w, const float* __restrict__ fc1b,
                            const float* __restrict__ fc2w, const float* __restrict__ fc2b,
                            float* __restrict__ out)
{
    __shared__ float pool[256];
    __shared__ float hid[128];
    int b = blockIdx.x, tid = threadIdx.x;
    float s = 0.f;
    const float* p = ao + (long)b*Tz*Hz + tid;
    for (int t = 0; t < Tz; t++) s += p[(long)t*Hz];
    pool[tid] = s * (1.f/512.f);
    __syncthreads();
    if (tid < 128) {
        float a = fc1b[tid];
        const float* w = fc1w + tid*256;
        #pragma unroll 8
        for (int k = 0; k < 256; k++) a += w[k]*pool[k];
        hid[tid] = fmaxf(a, 0.f);
    }
    __syncthreads();
    if (tid < 8) {
        float a = fc2b[tid];
        const float* w = fc2w + tid*128;
        #pragma unroll 8
        for (int k = 0; k < 128; k++) a += w[k]*hid[k];
        out[b*8 + tid] = a;
    }
}

// ---------------- launch ----------------
extern "C" void kernel_launch(void* const* d_in, const int* in_sizes, int n_in,
                              void* d_out, int out_size)
{
    const float* x         = (const float*)d_in[0];
    const float* W_ih0     = (const float*)d_in[1];
    const float* W_hh0     = (const float*)d_in[2];
    const float* b_ih0     = (const float*)d_in[3];
    const float* b_hh0     = (const float*)d_in[4];
    const float* W_ih1     = (const float*)d_in[5];
    const float* W_hh1     = (const float*)d_in[6];
    const float* b_ih1     = (const float*)d_in[7];
    const float* b_hh1     = (const float*)d_in[8];
    const float* gat_W     = (const float*)d_in[9];
    const float* gat_a     = (const float*)d_in[10];
    const float* ln_g      = (const float*)d_in[11];
    const float* ln_b      = (const float*)d_in[12];
    const float* mha_in_w  = (const float*)d_in[13];
    const float* mha_in_b  = (const float*)d_in[14];
    const float* mha_out_w = (const float*)d_in[15];
    const float* mha_out_b = (const float*)d_in[16];
    const float* fc1_w     = (const float*)d_in[17];
    const float* fc1_b     = (const float*)d_in[18];
    const float* fc2_w     = (const float*)d_in[19];
    const float* fc2_b     = (const float*)d_in[20];
    float* out = (float*)d_out;

    float *xp, *g0, *g1, *hh, *fs, *fd, *gato, *y, *qkv, *scores, *ctx, *ao, *wcat;
    cudaGetSymbolAddress((void**)&xp,     d_xp);
    cudaGetSymbolAddress((void**)&g0,     d_g0);
    cudaGetSymbolAddress((void**)&g1,     d_g1);
    cudaGetSymbolAddress((void**)&hh,     d_hh);
    cudaGetSymbolAddress((void**)&fs,     d_fs);
    cudaGetSymbolAddress((void**)&fd,     d_fd);
    cudaGetSymbolAddress((void**)&gato,   d_gato);
    cudaGetSymbolAddress((void**)&y,      d_y);
    cudaGetSymbolAddress((void**)&qkv,    d_qkv);
    cudaGetSymbolAddress((void**)&scores, d_scores);
    cudaGetSymbolAddress((void**)&ctx,    d_ctx);
    cudaGetSymbolAddress((void**)&ao,     d_ao);
    cudaGetSymbolAddress((void**)&wcat,   d_wcat);

    cudaFuncSetAttribute(gat_attn_kernel, cudaFuncAttributeMaxDynamicSharedMemorySize,
                         GAT_SMEM_BYTES);

    // xp0 = x @ W_ih0^T + b_ih0   (M=16384, N=768, K=128)
    gemm_tiled<true><<<dim3(12,128,1),256>>>(x, W_ih0, b_ih0, xp,
        Bz*Tz, G3H, INz, INz, INz, G3H, 1.f, 0,0,0,0,0,0, 1);
    // GRU layer 0
    gru_layer_kernel<<<128,384>>>(xp, W_hh0, b_hh0, g0);
    // xp1 = g0 @ W_ih1^T + b_ih1  (K=256)
    gemm_tiled<true><<<dim3(12,128,1),256>>>(g0, W_ih1, b_ih1, xp,
        Bz*Tz, G3H, Hz, Hz, Hz, G3H, 1.f, 0,0,0,0,0,0, 1);
    // GRU layer 1
    gru_layer_kernel<<<128,384>>>(xp, W_hh1, b_hh1, g1);

    // GAT projections
    pack_gatw_kernel<<<256,256>>>(gat_W, wcat);
    gemm_tiled<true><<<dim3(4,128,1),256>>>(g1, wcat, (const float*)0, hh,
        Bz*Tz, Hz, Hz, Hz, Hz, Hz, 1.f, 0,0,0,0,0,0, 1);
    fsfd_kernel<<<256,256>>>(hh, gat_a, fs, fd);
    gat_attn_kernel<<<128,256,GAT_SMEM_BYTES>>>(hh, fs, fd, gato);

    // y = LN(g1 + gat_out)
    ln_kernel<<<2048,256>>>(g1, gato, ln_g, ln_b, y);

    // qkv = y @ mha_in_w^T + b
    gemm_tiled<true><<<dim3(12,128,1),256>>>(y, mha_in_w, mha_in_b, qkv,
        Bz*Tz, G3H, Hz, Hz, Hz, G3H, 1.f, 0,0,0,0,0,0, 1);

    // scores = q @ k^T / 8   (batched over b,h; M=512,N=512,K=64)
    gemm_tiled<true><<<dim3(8,4,128),256>>>(qkv, qkv + 256, (const float*)0, scores,
        Tz, Tz, HDz, G3H, G3H, Tz, 0.125f,
        (long)Tz*G3H, 64L, (long)Tz*G3H, 64L,
        (long)NHEADz*Tz*Tz, (long)Tz*Tz, NHEADz);
    softmax_rows_kernel<<<8192,256>>>(scores);
    // ctx = attn @ v  (M=512,N=64,K=512)
    gemm_tiled<false><<<dim3(1,4,128),256>>>(scores, qkv + 512, (const float*)0, ctx,
        Tz, HDz, Tz, Tz, G3H, Hz, 1.f,
        (long)NHEADz*Tz*Tz, (long)Tz*Tz, (long)Tz*G3H, 64L,
        (long)Tz*Hz, 64L, NHEADz);
    // out-proj
    gemm_tiled<true><<<dim3(4,128,1),256>>>(ctx, mha_out_w, mha_out_b, ao,
        Bz*Tz, Hz, Hz, Hz, Hz, Hz, 1.f, 0,0,0,0,0,0, 1);

    // pooled -> fc1 -> fc2
    head_kernel<<<32,256>>>(ao, fc1_w, fc1_b, fc2_w, fc2_b, out);
}

// round 9
// speedup vs baseline: 1.2890x; 1.2834x over previous
#include <cuda_runtime.h>
#include <cuda_bf16.h>
#include <math.h>
#include <stdint.h>

#define Bz  32
#define Tz  512
#define INz 128
#define Hz  256
#define G3H 768
#define NHEADz 4
#define HDz 64
#define Cz 8

// ---------------- device scratch ----------------
__device__ float d_xp   [Bz*Tz*G3H];
__device__ float d_g0   [Bz*Tz*Hz];
__device__ float d_g1   [Bz*Tz*Hz];
__device__ float d_hh   [Bz*Tz*Hz];
__device__ float d_fs   [Bz*Tz*NHEADz];
__device__ float d_fd   [Bz*Tz*NHEADz];
__device__ float d_gato [Bz*Tz*Hz];
__device__ float d_y    [Bz*Tz*Hz];
__device__ float d_qkv  [Bz*Tz*G3H];
__device__ float d_scores[(long)Bz*NHEADz*Tz*Tz];
__device__ float d_ctx  [Bz*Tz*Hz];
__device__ float d_ao   [Bz*Tz*Hz];
__device__ float d_wcat [Hz*Hz];

// ---------------- tiled GEMM: 128x64 tile, 8x4 micro, double-buffered ----------------
// Requires M%128==0, N%64==0, K%16==0 (true for all call sites).
template<bool TRANSB>
__global__ void __launch_bounds__(256) gemm_tiled(
    const float* __restrict__ A, const float* __restrict__ Bm,
    const float* __restrict__ bias, float* __restrict__ C,
    int M, int N, int K, int lda, int ldb, int ldc, float alpha,
    long oAb, long oAh, long oBb, long oBh, long oCb, long oCh, int nH)
{
    int z = blockIdx.z;
    int zb = z / nH, zh = z - zb*nH;
    const float* Ab = A  + zb*oAb + zh*oAh;
    const float* Bb = Bm + zb*oBb + zh*oBh;
    float*       Cb = C  + zb*oCb + zh*oCh;

    __shared__ float As[2][16][132];
    __shared__ float Bs[2][16][68];

    int tid = threadIdx.x;
    int tx = tid & 15, ty = tid >> 4;
    int m0 = blockIdx.y * 128, n0 = blockIdx.x * 64;

    // loaders
    int ak  = (tid & 3) * 4;     // k offset (float4)
    int am  = tid >> 2;          // 0..63 (A row; +64 for second half)
    int bn  = tid >> 2;          // 0..63 (B row, TRANSB)
    int nk  = tid >> 4;          // 0..15 (B k row, non-TRANSB)
    int nn4 = (tid & 15) * 4;    // B n offset (non-TRANSB)

    const float* Aptr  = Ab + (long)(m0 + am) * lda + ak;
    const float* Aptr2 = Aptr + (long)64 * lda;
    const float* Bptr  = TRANSB ? (Bb + (long)(n0 + bn) * ldb + ak)
                                : (Bb + (long)nk * ldb + n0 + nn4);

    float4 a0 = *(const float4*)Aptr;
    float4 a1 = *(const float4*)Aptr2;
    float4 b0 = *(const float4*)Bptr;

    // stage 0
    As[0][ak+0][am] = a0.x; As[0][ak+1][am] = a0.y; As[0][ak+2][am] = a0.z; As[0][ak+3][am] = a0.w;
    As[0][ak+0][am+64] = a1.x; As[0][ak+1][am+64] = a1.y; As[0][ak+2][am+64] = a1.z; As[0][ak+3][am+64] = a1.w;
    if (TRANSB) {
        Bs[0][ak+0][bn] = b0.x; Bs[0][ak+1][bn] = b0.y; Bs[0][ak+2][bn] = b0.z; Bs[0][ak+3][bn] = b0.w;
    } else {
        *(float4*)&Bs[0][nk][nn4] = b0;
    }
    __syncthreads();

    int KB = K >> 4;
    float acc[8][4] = {};

    for (int kb = 0; kb < KB; kb++) {
        int cur = kb & 1;
        bool more = (kb + 1 < KB);
        if (more) {
            Aptr += 16; Aptr2 += 16;
            if (TRANSB) Bptr += 16; else Bptr += (long)16 * ldb;
            a0 = *(const float4*)Aptr;
            a1 = *(const float4*)Aptr2;
            b0 = *(const float4*)Bptr;
        }
        #pragma unroll
        for (int kk = 0; kk < 16; kk++) {
            float a[8], b[4];
            *(float4*)(a)     = *(const float4*)&As[cur][kk][ty*8];
            *(float4*)(a + 4) = *(const float4*)&As[cur][kk][ty*8 + 4];
            *(float4*)(b)     = *(const float4*)&Bs[cur][kk][tx*4];
            #pragma unroll
            for (int i = 0; i < 8; i++)
                #pragma unroll
                for (int j = 0; j < 4; j++)
                    acc[i][j] += a[i] * b[j];
        }
        if (more) {
            int nxt = cur ^ 1;
            As[nxt][ak+0][am] = a0.x; As[nxt][ak+1][am] = a0.y; As[nxt][ak+2][am] = a0.z; As[nxt][ak+3][am] = a0.w;
            As[nxt][ak+0][am+64] = a1.x; As[nxt][ak+1][am+64] = a1.y; As[nxt][ak+2][am+64] = a1.z; As[nxt][ak+3][am+64] = a1.w;
            if (TRANSB) {
                Bs[nxt][ak+0][bn] = b0.x; Bs[nxt][ak+1][bn] = b0.y; Bs[nxt][ak+2][bn] = b0.z; Bs[nxt][ak+3][bn] = b0.w;
            } else {
                *(float4*)&Bs[nxt][nk][nn4] = b0;
            }
        }
        __syncthreads();
    }

    float bb[4] = {0.f, 0.f, 0.f, 0.f};
    if (bias) {
        #pragma unroll
        for (int j = 0; j < 4; j++) bb[j] = bias[n0 + tx*4 + j];
    }
    #pragma unroll
    for (int i = 0; i < 8; i++) {
        int m = m0 + ty*8 + i;
        float4 v;
        v.x = alpha*acc[i][0] + bb[0];
        v.y = alpha*acc[i][1] + bb[1];
        v.z = alpha*acc[i][2] + bb[2];
        v.w = alpha*acc[i][3] + bb[3];
        *(float4*)&Cb[(long)m*ldc + n0 + tx*4] = v;
    }
}

// ---------------- GRU recurrence (round-6 proven version) ----------------
__device__ __forceinline__ float sigm(float x) { return 1.f / (1.f + __expf(-x)); }

__device__ __forceinline__ unsigned long long fma2(unsigned long long a,
                                                   unsigned long long b,
                                                   unsigned long long c) {
    unsigned long long d;
    asm("fma.rn.f32x2 %0, %1, %2, %3;" : "=l"(d) : "l"(a), "l"(b), "l"(c));
    return d;
}
__device__ __forceinline__ unsigned long long add2(unsigned long long a,
                                                   unsigned long long b) {
    unsigned long long d;
    asm("add.rn.f32x2 %0, %1, %2;" : "=l"(d) : "l"(a), "l"(b));
    return d;
}

// Thread map (per CTA, 384 threads = 12 warps):
//   khalf   = wid & 1          -> warp-uniform k-half => broadcast LDS (no bank conflicts)
//   r_local = (wid>>1)*32+lane -> 192 rows (3 gates x 64 outputs)
__global__ void __cluster_dims__(4,1,1) __launch_bounds__(384,1)
gru_layer_kernel(const float* __restrict__ xp, const float* __restrict__ W_hh,
                 const float* __restrict__ b_hh, float* __restrict__ gout)
{
    __shared__ __align__(16) float h_buf[2][256];
    __shared__ float gate_part[2][192];

    int tid = threadIdx.x;
    unsigned c;
    asm("mov.u32 %0, %%cluster_ctarank;" : "=r"(c));
    int b = blockIdx.x >> 2;

    int wid  = tid >> 5, lane = tid & 31;
    int khalf   = wid & 1;
    int r_local = (wid >> 1) * 32 + lane;   // 0..191
    int gate    = r_local >> 6;             // 0=r 1=z 2=n
    int iloc    = r_local & 63;
    int row     = gate*256 + (int)c*64 + iloc;

    // 128 weights as 64 packed f32x2 registers
    unsigned long long wreg2[64];
    {
        const unsigned long long* wp =
            (const unsigned long long*)(W_hh + (long)row*256 + khalf*128);
        #pragma unroll
        for (int kk = 0; kk < 64; kk++) wreg2[kk] = wp[kk];
    }
    float bh = (khalf == 0) ? b_hh[row] : 0.f;

    if (tid < 256) { h_buf[0][tid] = 0.f; h_buf[1][tid] = 0.f; }
    asm volatile("barrier.cluster.arrive.aligned;" ::: "memory");
    asm volatile("barrier.cluster.wait.aligned;"   ::: "memory");

    const float* xpb = xp   + (long)b*Tz*G3H;
    float*       gob = gout + (long)b*Tz*Hz;

    // x prefetch for t=0
    float xr = 0.f, xz = 0.f, xn = 0.f;
    if (tid < 64) {
        const float* xpt = xpb + (int)c*64 + tid;
        xr = xpt[0]; xz = xpt[256]; xn = xpt[512];
    }

    for (int t = 0; t < Tz; t++) {
        int cur = t & 1;
        float hprev = 0.f;
        if (tid < 64) hprev = h_buf[cur][(int)c*64 + tid];

        // h @ W_hh^T : warp-uniform (broadcast) LDS.128 + packed fma2, 4 accumulators
        unsigned long long acc2[4] = {0ull, 0ull, 0ull, 0ull};
        const ulonglong2* h2 = (const ulonglong2*)(&h_buf[cur][khalf*128]);
        #pragma unroll
        for (int q = 0; q < 32; q++) {
            ulonglong2 hv = h2[q];
            acc2[(2*q) & 3]   = fma2(wreg2[2*q],   hv.x, acc2[(2*q) & 3]);
            acc2[(2*q+1) & 3] = fma2(wreg2[2*q+1], hv.y, acc2[(2*q+1) & 3]);
        }
        unsigned long long s2 = add2(add2(acc2[0], acc2[1]), add2(acc2[2], acc2[3]));
        float2 sf = *(float2*)&s2;
        gate_part[khalf][r_local] = sf.x + sf.y + bh;
        __syncthreads();

        if (tid < 64) {
            float gr = gate_part[0][tid]       + gate_part[1][tid];
            float gz = gate_part[0][64 + tid]  + gate_part[1][64 + tid];
            float gn = gate_part[0][128 + tid] + gate_part[1][128 + tid];
            float r  = sigm(xr + gr);
            float zg = sigm(xz + gz);
            float n  = __tanhf(xn + r*gn);
            float hn = (1.f - zg)*n + zg*hprev;
            gob[(long)t*Hz + (int)c*64 + tid] = hn;
            if (t < Tz - 1) {
                int nxt = cur ^ 1;
                uint32_t laddr = (uint32_t)__cvta_generic_to_shared(&h_buf[nxt][(int)c*64 + tid]);
                #pragma unroll
                for (int p = 0; p < 4; p++) {
                    uint32_t ra;
                    asm volatile("mapa.shared::cluster.u32 %0, %1, %2;" : "=r"(ra) : "r"(laddr), "r"(p));
                    asm volatile("st.shared::cluster.f32 [%0], %1;" :: "r"(ra), "f"(hn) : "memory");
                }
                // prefetch x for t+1 (overlaps the cluster barrier)
                const float* xpt = xpb + (long)(t+1)*G3H + (int)c*64 + tid;
                xr = xpt[0]; xz = xpt[256]; xn = xpt[512];
            }
        }
        asm volatile("barrier.cluster.arrive.aligned;" ::: "memory");
        asm volatile("barrier.cluster.wait.aligned;"   ::: "memory");
    }
}

// ---------------- GAT weight pack ----------------
__global__ void pack_gatw_kernel(const float* __restrict__ gw, float* __restrict__ wcat)
{
    int idx = blockIdx.x*256 + threadIdx.x;   // 65536
    int n = idx >> 8, k = idx & 255;
    int head = n >> 6, o = n & 63;
    wcat[idx] = gw[head*(256*64) + k*64 + o];
}

// ---------------- f_src / f_dst ----------------
__global__ void fsfd_kernel(const float* __restrict__ hh, const float* __restrict__ ga,
                            float* __restrict__ fs, float* __restrict__ fd)
{
    int idx = blockIdx.x*256 + threadIdx.x;   // B*T*4
    int bt = idx >> 2, head = idx & 3;
    const float* hp = hh + (long)bt*Hz + head*64;
    const float* ap = ga + head*128;
    float s = 0.f, dsum = 0.f;
    #pragma unroll 8
    for (int o = 0; o < 64; o++) { float v = hp[o]; s += v*ap[o]; dsum += v*ap[64+o]; }
    fs[idx] = s; fd[idx] = dsum;
}

// ---------------- fused GAT attention ----------------
#define GAT_SMEM_BYTES (512*64*4 + 8*512*4*4 + 512*4 + 512*4)
__global__ void __launch_bounds__(256,1) gat_attn_kernel(
    const float* __restrict__ hh, const float* __restrict__ fs,
    const float* __restrict__ fd, float* __restrict__ gato)
{
    extern __shared__ float sm[];
    float* hs    = sm;                  // 512*64
    float* wbuf  = sm + 512*64;         // 8 warps * 512 * 4
    float* fs_s  = wbuf + 8*512*4;      // 512
    float* fd_s  = fs_s + 512;          // 512
    __shared__ float redbuf[8];
    __shared__ float maxfd_s;

    int b = blockIdx.x >> 2, head = blockIdx.x & 3;
    int tid = threadIdx.x, lane = tid & 31, warp = tid >> 5;

    const float* hhb = hh + ((long)b*Tz)*Hz + head*64;
    for (int idx = tid; idx < 512*64; idx += 256) {
        int j = idx >> 6, d = idx & 63;
        hs[idx] = hhb[(long)j*Hz + d];
    }
    for (int j = tid; j < 512; j += 256) {
        fs_s[j] = fs[((long)b*Tz + j)*NHEADz + head];
        fd_s[j] = fd[((long)b*Tz + j)*NHEADz + head];
    }
    __syncthreads();

    float mloc = -INFINITY;
    for (int j = tid; j < 512; j += 256) mloc = fmaxf(mloc, fd_s[j]);
    #pragma unroll
    for (int o = 16; o; o >>= 1) mloc = fmaxf(mloc, __shfl_xor_sync(~0u, mloc, o));
    if (lane == 0) redbuf[warp] = mloc;
    __syncthreads();
    if (tid == 0) {
        float m = redbuf[0];
        #pragma unroll
        for (int i = 1; i < 8; i++) m = fmaxf(m, redbuf[i]);
        maxfd_s = m;
    }
    __syncthreads();
    float maxfd = maxfd_s;

    float* wb = wbuf + warp*512*4;
    const float2* hs2 = (const float2*)hs;

    for (int pass = 0; pass < 16; pass++) {
        int i0 = warp*64 + pass*4;
        float fsv[4], mi[4], ssum[4] = {0.f,0.f,0.f,0.f};
        #pragma unroll
        for (int ii = 0; ii < 4; ii++) {
            fsv[ii] = fs_s[i0 + ii];
            float mm = fsv[ii] + maxfd;
            mi[ii] = mm > 0.f ? mm : 0.2f*mm;
        }
        for (int j = lane; j < 512; j += 32) {
            float fdv = fd_s[j];
            float4 wv; float e;
            e = fsv[0] + fdv; e = e > 0.f ? e : 0.2f*e; wv.x = __expf(e - mi[0]); ssum[0] += wv.x;
            e = fsv[1] + fdv; e = e > 0.f ? e : 0.2f*e; wv.y = __expf(e - mi[1]); ssum[1] += wv.y;
            e = fsv[2] + fdv; e = e > 0.f ? e : 0.2f*e; wv.z = __expf(e - mi[2]); ssum[2] += wv.z;
            e = fsv[3] + fdv; e = e > 0.f ? e : 0.2f*e; wv.w = __expf(e - mi[3]); ssum[3] += wv.w;
            *(float4*)(wb + j*4) = wv;
        }
        #pragma unroll
        for (int ii = 0; ii < 4; ii++)
            #pragma unroll
            for (int o = 16; o; o >>= 1) ssum[ii] += __shfl_xor_sync(~0u, ssum[ii], o);
        float rinv[4];
        #pragma unroll
        for (int ii = 0; ii < 4; ii++) rinv[ii] = 1.f / ssum[ii];
        __syncwarp();

        float2 acc[4] = {{0.f,0.f},{0.f,0.f},{0.f,0.f},{0.f,0.f}};
        const float4* wb4 = (const float4*)wb;
        #pragma unroll 4
        for (int j = 0; j < 512; j++) {
            float4 wv = wb4[j];
            float2 hv = hs2[j*32 + lane];
            acc[0].x += wv.x*hv.x; acc[0].y += wv.x*hv.y;
            acc[1].x += wv.y*hv.x; acc[1].y += wv.y*hv.y;
            acc[2].x += wv.z*hv.x; acc[2].y += wv.z*hv.y;
            acc[3].x += wv.w*hv.x; acc[3].y += wv.w*hv.y;
        }
        #pragma unroll
        for (int ii = 0; ii < 4; ii++) {
            long o = ((long)b*Tz + i0 + ii)*Hz + head*64 + lane*2;
            float2 v; v.x = acc[ii].x*rinv[ii]; v.y = acc[ii].y*rinv[ii];
            *(float2*)(gato + o) = v;
        }
        __syncwarp();
    }
}

// ---------------- LayerNorm(g + gato) ----------------
__global__ void ln_kernel(const float* __restrict__ g, const float* __restrict__ go,
                          const float* __restrict__ gam, const float* __restrict__ bet,
                          float* __restrict__ y)
{
    int row = blockIdx.x*8 + (threadIdx.x >> 5);
    int lane = threadIdx.x & 31;
    const float* gp  = g  + (long)row*Hz + lane*8;
    const float* gop = go + (long)row*Hz + lane*8;
    float v[8]; float s = 0.f, ss = 0.f;
    #pragma unroll
    for (int k = 0; k < 8; k++) { v[k] = gp[k] + gop[k]; s += v[k]; ss += v[k]*v[k]; }
    #pragma unroll
    for (int o = 16; o; o >>= 1) {
        s  += __shfl_xor_sync(~0u, s,  o);
        ss += __shfl_xor_sync(~0u, ss, o);
    }
    float mu = s * (1.f/256.f);
    float var = ss * (1.f/256.f) - mu*mu;
    float rstd = rsqrtf(var + 1e-5f);
    float* yp = y + (long)row*Hz + lane*8;
    #pragma unroll
    for (int k = 0; k < 8; k++) {
        int col = lane*8 + k;
        yp[k] = (v[k] - mu) * rstd * gam[col] + bet[col];
    }
}

// ---------------- row softmax ----------------
__global__ void softmax_rows_kernel(float* __restrict__ s)
{
    long row = (long)blockIdx.x*8 + (threadIdx.x >> 5);
    int lane = threadIdx.x & 31;
    float4* p = (float4*)(s + row*512);
    float4 v[4];
    float m = -INFINITY;
    #pragma unroll
    for (int q = 0; q < 4; q++) {
        v[q] = p[lane + 32*q];
        m = fmaxf(m, fmaxf(fmaxf(v[q].x, v[q].y), fmaxf(v[q].z, v[q].w)));
    }
    #pragma unroll
    for (int o = 16; o; o >>= 1) m = fmaxf(m, __shfl_xor_sync(~0u, m, o));
    float sum = 0.f;
    #pragma unroll
    for (int q = 0; q < 4; q++) {
        v[q].x = __expf(v[q].x - m); v[q].y = __expf(v[q].y - m);
        v[q].z = __expf(v[q].z - m); v[q].w = __expf(v[q].w - m);
        sum += v[q].x + v[q].y + v[q].z + v[q].w;
    }
    #pragma unroll
    for (int o = 16; o; o >>= 1) sum += __shfl_xor_sync(~0u, sum, o);
    float r = 1.f / sum;
    #pragma unroll
    for (int q = 0; q < 4; q++) {
        v[q].x *= r; v[q].y *= r; v[q].z *= r; v[q].w *= r;
        p[lane + 32*q] = v[q];
    }
}

// ---------------- pooled head ----------------
__global__ void head_kernel(const float* __restrict__ ao,
                            const float* __restrict__ fc1w, const float* __restrict__ fc1b,
                            const float* __restrict__ fc2w, const float* __restrict__ fc2b,
                            float* __restrict__ out)
{
    __shared__ float pool[256];
    __shared__ float hid[128];
    int b = blockIdx.x, tid = threadIdx.x;
    float s = 0.f;
    const float* p = ao + (long)b*Tz*Hz + tid;
    for (int t = 0; t < Tz; t++) s += p[(long)t*Hz];
    pool[tid] = s * (1.f/512.f);
    __syncthreads();
    if (tid < 128) {
        float a = fc1b[tid];
        const float* w = fc1w + tid*256;
        #pragma unroll 8
        for (int k = 0; k < 256; k++) a += w[k]*pool[k];
        hid[tid] = fmaxf(a, 0.f);
    }
    __syncthreads();
    if (tid < 8) {
        float a = fc2b[tid];
        const float* w = fc2w + tid*128;
        #pragma unroll 8
        for (int k = 0; k < 128; k++) a += w[k]*hid[k];
        out[b*8 + tid] = a;
    }
}

// ---------------- launch ----------------
extern "C" void kernel_launch(void* const* d_in, const int* in_sizes, int n_in,
                              void* d_out, int out_size)
{
    const float* x         = (const float*)d_in[0];
    const float* W_ih0     = (const float*)d_in[1];
    const float* W_hh0     = (const float*)d_in[2];
    const float* b_ih0     = (const float*)d_in[3];
    const float* b_hh0     = (const float*)d_in[4];
    const float* W_ih1     = (const float*)d_in[5];
    const float* W_hh1     = (const float*)d_in[6];
    const float* b_ih1     = (const float*)d_in[7];
    const float* b_hh1     = (const float*)d_in[8];
    const float* gat_W     = (const float*)d_in[9];
    const float* gat_a     = (const float*)d_in[10];
    const float* ln_g      = (const float*)d_in[11];
    const float* ln_b      = (const float*)d_in[12];
    const float* mha_in_w  = (const float*)d_in[13];
    const float* mha_in_b  = (const float*)d_in[14];
    const float* mha_out_w = (const float*)d_in[15];
    const float* mha_out_b = (const float*)d_in[16];
    const float* fc1_w     = (const float*)d_in[17];
    const float* fc1_b     = (const float*)d_in[18];
    const float* fc2_w     = (const float*)d_in[19];
    const float* fc2_b     = (const float*)d_in[20];
    float* out = (float*)d_out;

    float *xp, *g0, *g1, *hh, *fs, *fd, *gato, *y, *qkv, *scores, *ctx, *ao, *wcat;
    cudaGetSymbolAddress((void**)&xp,     d_xp);
    cudaGetSymbolAddress((void**)&g0,     d_g0);
    cudaGetSymbolAddress((void**)&g1,     d_g1);
    cudaGetSymbolAddress((void**)&hh,     d_hh);
    cudaGetSymbolAddress((void**)&fs,     d_fs);
    cudaGetSymbolAddress((void**)&fd,     d_fd);
    cudaGetSymbolAddress((void**)&gato,   d_gato);
    cudaGetSymbolAddress((void**)&y,      d_y);
    cudaGetSymbolAddress((void**)&qkv,    d_qkv);
    cudaGetSymbolAddress((void**)&scores, d_scores);
    cudaGetSymbolAddress((void**)&ctx,    d_ctx);
    cudaGetSymbolAddress((void**)&ao,     d_ao);
    cudaGetSymbolAddress((void**)&wcat,   d_wcat);

    cudaFuncSetAttribute(gat_attn_kernel, cudaFuncAttributeMaxDynamicSharedMemorySize,
                         GAT_SMEM_BYTES);

    // xp0 = x @ W_ih0^T + b_ih0   (M=16384, N=768, K=128)
    gemm_tiled<true><<<dim3(12,128,1),256>>>(x, W_ih0, b_ih0, xp,
        Bz*Tz, G3H, INz, INz, INz, G3H, 1.f, 0,0,0,0,0,0, 1);
    // GRU layer 0
    gru_layer_kernel<<<128,384>>>(xp, W_hh0, b_hh0, g0);
    // xp1 = g0 @ W_ih1^T + b_ih1  (K=256)
    gemm_tiled<true><<<dim3(12,128,1),256>>>(g0, W_ih1, b_ih1, xp,
        Bz*Tz, G3H, Hz, Hz, Hz, G3H, 1.f, 0,0,0,0,0,0, 1);
    // GRU layer 1
    gru_layer_kernel<<<128,384>>>(xp, W_hh1, b_hh1, g1);

    // GAT projections
    pack_gatw_kernel<<<256,256>>>(gat_W, wcat);
    gemm_tiled<true><<<dim3(4,128,1),256>>>(g1, wcat, (const float*)0, hh,
        Bz*Tz, Hz, Hz, Hz, Hz, Hz, 1.f, 0,0,0,0,0,0, 1);
    fsfd_kernel<<<256,256>>>(hh, gat_a, fs, fd);
    gat_attn_kernel<<<128,256,GAT_SMEM_BYTES>>>(hh, fs, fd, gato);

    // y = LN(g1 + gat_out)
    ln_kernel<<<2048,256>>>(g1, gato, ln_g, ln_b, y);

    // qkv = y @ mha_in_w^T + b
    gemm_tiled<true><<<dim3(12,128,1),256>>>(y, mha_in_w, mha_in_b, qkv,
        Bz*Tz, G3H, Hz, Hz, Hz, G3H, 1.f, 0,0,0,0,0,0, 1);

    // scores = q @ k^T / 8   (batched over b,h; M=512,N=512,K=64)
    gemm_tiled<true><<<dim3(8,4,128),256>>>(qkv, qkv + 256, (const float*)0, scores,
        Tz, Tz, HDz, G3H, G3H, Tz, 0.125f,
        (long)Tz*G3H, 64L, (long)Tz*G3H, 64L,
        (long)NHEADz*Tz*Tz, (long)Tz*Tz, NHEADz);
    softmax_rows_kernel<<<8192,256>>>(scores);
    // ctx = attn @ v  (M=512,N=64,K=512)
    gemm_tiled<false><<<dim3(1,4,128),256>>>(scores, qkv + 512, (const float*)0, ctx,
        Tz, HDz, Tz, Tz, G3H, Hz, 1.f,
        (long)NHEADz*Tz*Tz, (long)Tz*Tz, (long)Tz*G3H, 64L,
        (long)Tz*Hz, 64L, NHEADz);
    // out-proj
    gemm_tiled<true><<<dim3(4,128,1),256>>>(ctx, mha_out_w, mha_out_b, ao,
        Bz*Tz, Hz, Hz, Hz, Hz, Hz, 1.f, 0,0,0,0,0,0, 1);

    // pooled -> fc1 -> fc2
    head_kernel<<<32,256>>>(ao, fc1_w, fc1_b, fc2_w, fc2_b, out);
}